// round 3
// baseline (speedup 1.0000x reference)
#include <cuda_runtime.h>
#include <cuda_bf16.h>
#include <cstdint>

// Shapes (fixed by dataset):
//   messages (B=32, E=8192, D=128) fp32 | tgt (B=32, E=8192) int32
//   out      (B=32, N=2048, D=128) fp32
static constexpr int B = 32;
static constexpr int E = 8192;
static constexpr int N = 2048;
static constexpr int D = 128;        // 32 float4 per row -> one warp handles a row
static constexpr int CAP = 16;       // bin capacity per (b,atom); Poisson(4) tail -> ~0
                                     // overflow handled correctly by phase 3

// Scratch (device globals: no allocations allowed in kernel_launch)
__device__ int g_count[B * N];          // 256 KB : edges per cell
__device__ int g_slot [B * E];          // 1 MiB  : slot assigned to each edge
__device__ int g_bins [B * N * CAP];    // 4 MiB  : edge ids per cell (first CAP)

// ── Phase 0: zero the per-cell counters ────────────────────────────────
__global__ void zero_counts() {
    int i = blockIdx.x * blockDim.x + threadIdx.x;
    if (i < B * N) g_count[i] = 0;
}

// ── Phase 1: bin edges by (batch, target) ─────────────────────────────
__global__ __launch_bounds__(256) void bin_edges(const int* __restrict__ tgt) {
    int e = blockIdx.x * 256 + threadIdx.x;          // global edge id [0, B*E)
    int t = __ldg(&tgt[e]);
    int cell = ((e >> 13) * N) + t;                  // b = e / E (E = 8192)
    int s = atomicAdd(&g_count[cell], 1);
    g_slot[e] = s;
    if (s < CAP) g_bins[cell * CAP + s] = e;
}

// ── Phase 2: gather — one warp per output atom row, no atomics ────────
// Writes EVERY cell (zeros included), so no output memset is needed.
__global__ __launch_bounds__(256) void gather(
    const float4* __restrict__ messages,   // (B*E, 32) float4
    float4*       __restrict__ out)        // (B*N, 32) float4
{
    const int lane = threadIdx.x & 31;
    const int cell = blockIdx.x * 8 + (threadIdx.x >> 5);  // 8 warps/block

    const int cnt = g_count[cell];
    const int c   = cnt < CAP ? cnt : CAP;

    // Coalesced bin fetch: lane i holds edge id i (i < c).
    int e = 0;
    if (lane < c) e = g_bins[cell * CAP + lane];

    float4 acc = make_float4(0.f, 0.f, 0.f, 0.f);

    // 4-wide batches: front-load up to 4 independent LDG.128 before adding.
    for (int i = 0; i < c; i += 4) {
        float4 v[4];
#pragma unroll
        for (int j = 0; j < 4; j++) {
            v[j] = make_float4(0.f, 0.f, 0.f, 0.f);
            if (i + j < c) {
                int row = __shfl_sync(0xFFFFFFFFu, e, i + j);
                v[j] = __ldcs(&messages[(size_t)row * 32 + lane]);
            }
        }
#pragma unroll
        for (int j = 0; j < 4; j++) {
            acc.x += v[j].x; acc.y += v[j].y;
            acc.z += v[j].z; acc.w += v[j].w;
        }
    }

    out[(size_t)cell * 32 + lane] = acc;
}

// ── Phase 3: overflow edges (slot >= CAP) — atomic fallback, ~0 work ──
__global__ __launch_bounds__(256) void overflow_add(
    const float4* __restrict__ messages,
    const int*    __restrict__ tgt,
    float*        __restrict__ out)
{
    int e = blockIdx.x * 256 + threadIdx.x;
    if (g_slot[e] < CAP) return;                     // common case: everyone exits
    int t = __ldg(&tgt[e]);
    int cell = ((e >> 13) * N) + t;
    const float4* src = &messages[(size_t)e * 32];
    float* dst = out + (size_t)cell * D;
    for (int k = 0; k < 32; k++) {
        float4 v = __ldg(&src[k]);
        asm volatile(
            "red.global.add.v4.f32 [%0], {%1, %2, %3, %4};"
            :: "l"(dst + k * 4), "f"(v.x), "f"(v.y), "f"(v.z), "f"(v.w)
            : "memory");
    }
}

extern "C" void kernel_launch(void* const* d_in, const int* in_sizes, int n_in,
                              void* d_out, int out_size)
{
    const float4* messages = (const float4*)d_in[0];
    const int*    tgt      = (const int*)d_in[1];

    zero_counts<<<(B * N + 255) / 256, 256>>>();
    bin_edges<<<(B * E) / 256, 256>>>(tgt);
    gather<<<(B * N) / 8, 256>>>(messages, (float4*)d_out);
    overflow_add<<<(B * E) / 256, 256>>>(messages, tgt, (float*)d_out);
}